// round 1
// baseline (speedup 1.0000x reference)
#include <cuda_runtime.h>
#include <math.h>

// ---------------------------------------------------------------------------
// MambaBlock: LN1 -> in_proj -> conv1d+SiLU -> x_proj -> dt_proj(softplus)
//             -> selective scan (+D, *silu(z)) -> out_proj (+residual)
//             -> LN2 -> MLP (GELU exact) (+residual)
// All fp32 SIMT for round 1. Scratch in __device__ globals (no allocs).
// ---------------------------------------------------------------------------

#define BATCH   4
#define SEQ     2048
#define DM      1024
#define DI      2048
#define DSTATE  16
#define DTR     64
#define HID     2048
#define NROWS   (BATCH * SEQ)      // 8192
#define XDBL_C  96                 // dt_rank + 2*d_state

// -------------------------- scratch buffers --------------------------------
__device__ float g_h   [NROWS * (size_t)DM];
__device__ float g_xz  [NROWS * (size_t)(2 * DI)];
__device__ float g_xa  [NROWS * (size_t)DI];
__device__ float g_xdbl[NROWS * (size_t)XDBL_C];
__device__ float g_delta[NROWS * (size_t)DI];
__device__ float g_y   [NROWS * (size_t)DI];
__device__ float g_x2  [NROWS * (size_t)DM];
__device__ float g_h2  [NROWS * (size_t)DM];
__device__ float g_m1  [NROWS * (size_t)HID];

// -------------------------- layernorm --------------------------------------
__device__ __forceinline__ float block_sum_256(float v, float* red) {
    #pragma unroll
    for (int o = 16; o; o >>= 1) v += __shfl_xor_sync(0xffffffffu, v, o);
    if ((threadIdx.x & 31) == 0) red[threadIdx.x >> 5] = v;
    __syncthreads();
    float t = (threadIdx.x < 8) ? red[threadIdx.x] : 0.0f;
    if (threadIdx.x < 32) {
        #pragma unroll
        for (int o = 4; o; o >>= 1) t += __shfl_xor_sync(0xffffffffu, t, o);
        if (threadIdx.x == 0) red[0] = t;
    }
    __syncthreads();
    float r = red[0];
    __syncthreads();
    return r;
}

__global__ __launch_bounds__(256) void ln_kernel(
    const float* __restrict__ x, const float* __restrict__ g,
    const float* __restrict__ b, float* __restrict__ out)
{
    __shared__ float red[8];
    int row = blockIdx.x;
    const float4* xr = reinterpret_cast<const float4*>(x + (size_t)row * DM);
    float4 v = xr[threadIdx.x];

    float s = v.x + v.y + v.z + v.w;
    s = block_sum_256(s, red);
    float mean = s * (1.0f / DM);

    float dx = v.x - mean, dy = v.y - mean, dz = v.z - mean, dw = v.w - mean;
    float q = dx * dx + dy * dy + dz * dz + dw * dw;
    q = block_sum_256(q, red);
    float rstd = rsqrtf(q * (1.0f / DM) + 1e-5f);

    const float4* gr = reinterpret_cast<const float4*>(g);
    const float4* br = reinterpret_cast<const float4*>(b);
    float4 gv = gr[threadIdx.x], bv = br[threadIdx.x];
    float4 o;
    o.x = dx * rstd * gv.x + bv.x;
    o.y = dy * rstd * gv.y + bv.y;
    o.z = dz * rstd * gv.z + bv.z;
    o.w = dw * rstd * gv.w + bv.w;
    reinterpret_cast<float4*>(out + (size_t)row * DM)[threadIdx.x] = o;
}

// -------------------------- GEMM: C = A(MxK) @ W(NxK)^T + epilogue ---------
// EPI: 0 plain, 1 bias+softplus, 2 +residual, 3 bias+gelu, 4 bias+residual
template <int EPI>
__global__ __launch_bounds__(256) void gemm_kernel(
    int M, int N, int K, int lda,
    const float* __restrict__ A, const float* __restrict__ W,
    const float* __restrict__ bias, const float* __restrict__ res,
    float* __restrict__ C)
{
    __shared__ float As[8][128];
    __shared__ float Ws[8][128];

    int tid = threadIdx.x;
    int m0 = blockIdx.y * 128;
    int n0 = blockIdx.x * 128;
    int lr = tid >> 1;             // 0..127 row within tile
    int kq = (tid & 1) * 4;        // 0 or 4
    int tx = tid & 15;             // 0..15
    int ty = tid >> 4;             // 0..15

    float acc[8][8];
    #pragma unroll
    for (int i = 0; i < 8; i++)
        #pragma unroll
        for (int j = 0; j < 8; j++) acc[i][j] = 0.0f;

    for (int k0 = 0; k0 < K; k0 += 8) {
        float4 av = *reinterpret_cast<const float4*>(
            A + (size_t)(m0 + lr) * lda + k0 + kq);
        float4 wv = make_float4(0.f, 0.f, 0.f, 0.f);
        if (n0 + lr < N)
            wv = *reinterpret_cast<const float4*>(
                W + (size_t)(n0 + lr) * K + k0 + kq);
        As[kq + 0][lr] = av.x; As[kq + 1][lr] = av.y;
        As[kq + 2][lr] = av.z; As[kq + 3][lr] = av.w;
        Ws[kq + 0][lr] = wv.x; Ws[kq + 1][lr] = wv.y;
        Ws[kq + 2][lr] = wv.z; Ws[kq + 3][lr] = wv.w;
        __syncthreads();

        #pragma unroll
        for (int k = 0; k < 8; k++) {
            float4 a0 = *reinterpret_cast<const float4*>(&As[k][ty * 8]);
            float4 a1 = *reinterpret_cast<const float4*>(&As[k][ty * 8 + 4]);
            float4 w0 = *reinterpret_cast<const float4*>(&Ws[k][tx * 8]);
            float4 w1 = *reinterpret_cast<const float4*>(&Ws[k][tx * 8 + 4]);
            float a[8] = {a0.x, a0.y, a0.z, a0.w, a1.x, a1.y, a1.z, a1.w};
            float w[8] = {w0.x, w0.y, w0.z, w0.w, w1.x, w1.y, w1.z, w1.w};
            #pragma unroll
            for (int i = 0; i < 8; i++)
                #pragma unroll
                for (int j = 0; j < 8; j++) acc[i][j] += a[i] * w[j];
        }
        __syncthreads();
    }

    #pragma unroll
    for (int i = 0; i < 8; i++) {
        int gm = m0 + ty * 8 + i;
        #pragma unroll
        for (int j = 0; j < 8; j++) {
            int gn = n0 + tx * 8 + j;
            if (gn < N) {
                float v = acc[i][j];
                if (EPI == 1) {                 // bias + softplus
                    v += bias[gn];
                    v = (v > 20.0f) ? v : log1pf(expf(v));
                } else if (EPI == 2) {          // + residual
                    v += res[(size_t)gm * N + gn];
                } else if (EPI == 3) {          // bias + gelu (exact)
                    v += bias[gn];
                    v = 0.5f * v * (1.0f + erff(v * 0.70710678118654752f));
                } else if (EPI == 4) {          // bias + residual
                    v += bias[gn] + res[(size_t)gm * N + gn];
                }
                C[(size_t)gm * N + gn] = v;
            }
        }
    }
}

// -------------------------- causal depthwise conv + SiLU -------------------
__global__ __launch_bounds__(256) void conv_silu_kernel(
    const float* __restrict__ conv_w, const float* __restrict__ conv_b)
{
    int idx = blockIdx.x * 256 + threadIdx.x;    // over NROWS*DI
    int d = idx & (DI - 1);
    int row = idx >> 11;                          // DI = 2048
    int l = row & (SEQ - 1);
    float acc = conv_b[d];
    #pragma unroll
    for (int k = 0; k < 4; k++) {
        int ls = l - 3 + k;
        if (ls >= 0)
            acc += g_xz[(size_t)(row - 3 + k) * (2 * DI) + d] * conv_w[d * 4 + k];
    }
    float sg = 1.0f / (1.0f + expf(-acc));
    g_xa[idx] = acc * sg;
}

// -------------------------- selective scan ---------------------------------
// One thread per channel d (16 states in registers). B/C staged per 64 steps.
// Fuses +u*D and *silu(z) into the store.
__global__ __launch_bounds__(64) void scan_kernel(
    const float* __restrict__ A_log, const float* __restrict__ Dp)
{
    int d = blockIdx.x * 64 + threadIdx.x;
    int batch = blockIdx.y;

    float Aa[DSTATE];
    #pragma unroll
    for (int n = 0; n < DSTATE; n++) Aa[n] = -expf(A_log[d * DSTATE + n]);
    float Dd = Dp[d];

    float h[DSTATE];
    #pragma unroll
    for (int n = 0; n < DSTATE; n++) h[n] = 0.0f;

    __shared__ float bc[64][32];   // [step][B(16) | C(16)]

    for (int l0 = 0; l0 < SEQ; l0 += 64) {
        int rowbase = batch * SEQ + l0;
        __syncthreads();
        for (int i = threadIdx.x; i < 64 * 32; i += 64) {
            int r = i >> 5, c = i & 31;
            bc[r][c] = g_xdbl[(size_t)(rowbase + r) * XDBL_C + DTR + c];
        }
        __syncthreads();

        for (int s = 0; s < 64; s++) {
            size_t idx = (size_t)(rowbase + s) * DI + d;
            float dlt = g_delta[idx];
            float u = g_xa[idx];
            float du = dlt * u;
            float yt = 0.0f;
            #pragma unroll
            for (int n = 0; n < DSTATE; n++) {
                float dA = __expf(dlt * Aa[n]);
                h[n] = h[n] * dA + du * bc[s][n];
                yt += h[n] * bc[s][DSTATE + n];
            }
            float zv = g_xz[(size_t)(rowbase + s) * (2 * DI) + DI + d];
            float sg = 1.0f / (1.0f + __expf(-zv));
            g_y[idx] = (yt + u * Dd) * (zv * sg);
        }
    }
}

// -------------------------- launch -----------------------------------------
extern "C" void kernel_launch(void* const* d_in, const int* in_sizes, int n_in,
                              void* d_out, int out_size)
{
    const float* x         = (const float*)d_in[0];
    const float* ln1_g     = (const float*)d_in[1];
    const float* ln1_b     = (const float*)d_in[2];
    const float* in_proj_w = (const float*)d_in[3];
    const float* conv_w    = (const float*)d_in[4];
    const float* conv_b    = (const float*)d_in[5];
    const float* x_proj_w  = (const float*)d_in[6];
    const float* dt_proj_w = (const float*)d_in[7];
    const float* dt_proj_b = (const float*)d_in[8];
    const float* A_log     = (const float*)d_in[9];
    const float* Dp        = (const float*)d_in[10];
    const float* out_proj_w= (const float*)d_in[11];
    const float* ln2_g     = (const float*)d_in[12];
    const float* ln2_b     = (const float*)d_in[13];
    const float* mlp_w1    = (const float*)d_in[14];
    const float* mlp_b1    = (const float*)d_in[15];
    const float* mlp_w2    = (const float*)d_in[16];
    const float* mlp_b2    = (const float*)d_in[17];
    float* out = (float*)d_out;

    float *ph, *pxz, *pxa, *pxdbl, *pdelta, *py, *px2, *ph2, *pm1;
    cudaGetSymbolAddress((void**)&ph,     g_h);
    cudaGetSymbolAddress((void**)&pxz,    g_xz);
    cudaGetSymbolAddress((void**)&pxa,    g_xa);
    cudaGetSymbolAddress((void**)&pxdbl,  g_xdbl);
    cudaGetSymbolAddress((void**)&pdelta, g_delta);
    cudaGetSymbolAddress((void**)&py,     g_y);
    cudaGetSymbolAddress((void**)&px2,    g_x2);
    cudaGetSymbolAddress((void**)&ph2,    g_h2);
    cudaGetSymbolAddress((void**)&pm1,    g_m1);

    // 1. LN1
    ln_kernel<<<NROWS, 256>>>(x, ln1_g, ln1_b, ph);

    // 2. in_proj: (8192,1024) @ (4096,1024)^T -> xz (8192,4096)
    gemm_kernel<0><<<dim3(2 * DI / 128, NROWS / 128), 256>>>(
        NROWS, 2 * DI, DM, DM, ph, in_proj_w, nullptr, nullptr, pxz);

    // 3. conv1d + SiLU -> xa (8192,2048)
    conv_silu_kernel<<<(NROWS * DI) / 256, 256>>>(conv_w, conv_b);

    // 4. x_proj: (8192,2048) @ (96,2048)^T -> x_dbl (8192,96)
    gemm_kernel<0><<<dim3(1, NROWS / 128), 256>>>(
        NROWS, XDBL_C, DI, DI, pxa, x_proj_w, nullptr, nullptr, pxdbl);

    // 5. dt_proj + softplus: (8192,64 view of x_dbl) @ (2048,64)^T -> delta
    gemm_kernel<1><<<dim3(DI / 128, NROWS / 128), 256>>>(
        NROWS, DI, DTR, XDBL_C, pxdbl, dt_proj_w, dt_proj_b, nullptr, pdelta);

    // 6. selective scan (+u*D, *silu(z)) -> y (8192,2048)
    scan_kernel<<<dim3(DI / 64, BATCH), 64>>>(A_log, Dp);

    // 7. out_proj + residual(x) -> x2 (8192,1024)
    gemm_kernel<2><<<dim3(DM / 128, NROWS / 128), 256>>>(
        NROWS, DM, DI, DI, py, out_proj_w, nullptr, x, px2);

    // 8. LN2
    ln_kernel<<<NROWS, 256>>>(px2, ln2_g, ln2_b, ph2);

    // 9. MLP up + GELU -> m1 (8192,2048)
    gemm_kernel<3><<<dim3(HID / 128, NROWS / 128), 256>>>(
        NROWS, HID, DM, DM, ph2, mlp_w1, mlp_b1, nullptr, pm1);

    // 10. MLP down + bias + residual(x2) -> out (8192,1024)
    gemm_kernel<4><<<dim3(DM / 128, NROWS / 128), 256>>>(
        NROWS, DM, HID, HID, pm1, mlp_w2, mlp_b2, px2, out);
}

// round 3
// speedup vs baseline: 1.6327x; 1.6327x over previous
#include <cuda_runtime.h>
#include <cuda_bf16.h>
#include <math.h>
#include <stdint.h>

// ---------------------------------------------------------------------------
// MambaBlock on GB300 (plain sm_103 target): GEMMs via mma.sync bf16 hi/lo
// split (3-product, fp32 accumulate), cp.async double-buffered pipeline.
// ---------------------------------------------------------------------------

#define BATCH   4
#define SEQ     2048
#define DM      1024
#define DI      2048
#define DSTATE  16
#define DTR     64
#define HID     2048
#define NROWS   (BATCH * SEQ)      // 8192
#define XC      96                 // dt_rank + 2*d_state

typedef __nv_bfloat16 bf16;

// -------------------------- scratch buffers --------------------------------
__device__ float g_xz   [NROWS * (size_t)(2 * DI)];
__device__ bf16  g_h_hi [NROWS * (size_t)DM];
__device__ bf16  g_h_lo [NROWS * (size_t)DM];
__device__ bf16  g_xa_hi[NROWS * (size_t)DI];
__device__ bf16  g_xa_lo[NROWS * (size_t)DI];
__device__ float g_xdbl [NROWS * (size_t)XC];
__device__ bf16  g_dt_hi[NROWS * (size_t)DTR];
__device__ bf16  g_dt_lo[NROWS * (size_t)DTR];
__device__ float g_delta[NROWS * (size_t)DI];
__device__ bf16  g_y_hi [NROWS * (size_t)DI];
__device__ bf16  g_y_lo [NROWS * (size_t)DI];
__device__ float g_x2   [NROWS * (size_t)DM];
__device__ bf16  g_h2_hi[NROWS * (size_t)DM];
__device__ bf16  g_h2_lo[NROWS * (size_t)DM];
__device__ bf16  g_m1_hi[NROWS * (size_t)HID];
__device__ bf16  g_m1_lo[NROWS * (size_t)HID];
// weight hi/lo planes
__device__ bf16 g_wip_h[(size_t)(2*DI) * DM],  g_wip_l[(size_t)(2*DI) * DM];
__device__ bf16 g_wxp_h[(size_t)XC * DI],      g_wxp_l[(size_t)XC * DI];
__device__ bf16 g_wdt_h[(size_t)DI * DTR],     g_wdt_l[(size_t)DI * DTR];
__device__ bf16 g_wop_h[(size_t)DM * DI],      g_wop_l[(size_t)DM * DI];
__device__ bf16 g_wm1_h[(size_t)HID * DM],     g_wm1_l[(size_t)HID * DM];
__device__ bf16 g_wm2_h[(size_t)DM * HID],     g_wm2_l[(size_t)DM * HID];

// -------------------------- PTX helpers ------------------------------------
__device__ __forceinline__ uint32_t smem_u32(const void* p) {
    uint32_t a;
    asm("{ .reg .u64 t; cvta.to.shared.u64 t, %1; cvt.u32.u64 %0, t; }"
        : "=r"(a) : "l"(p));
    return a;
}

__device__ __forceinline__ void cp16(uint32_t dst, const void* src) {
    asm volatile("cp.async.cg.shared.global [%0], [%1], 16;"
                 :: "r"(dst), "l"(src));
}

__device__ __forceinline__ void cp16p(uint32_t dst, const void* src, bool pred) {
    int sz = pred ? 16 : 0;
    asm volatile("cp.async.cg.shared.global [%0], [%1], 16, %2;"
                 :: "r"(dst), "l"(src), "r"(sz));
}

#define CP_COMMIT() asm volatile("cp.async.commit_group;")
#define CP_WAIT(n)  asm volatile("cp.async.wait_group %0;" :: "n"(n))

#define LDSM4(R, addr) \
    asm volatile("ldmatrix.sync.aligned.m8n8.x4.shared.b16 {%0,%1,%2,%3}, [%4];" \
        : "=r"((R)[0]), "=r"((R)[1]), "=r"((R)[2]), "=r"((R)[3]) : "r"(addr))

__device__ __forceinline__ void mma16816(float* c, const uint32_t* a,
                                         uint32_t b0, uint32_t b1) {
    asm volatile(
        "mma.sync.aligned.m16n8k16.row.col.f32.bf16.bf16.f32 "
        "{%0,%1,%2,%3}, {%4,%5,%6,%7}, {%8,%9}, {%0,%1,%2,%3};"
        : "+f"(c[0]), "+f"(c[1]), "+f"(c[2]), "+f"(c[3])
        : "r"(a[0]), "r"(a[1]), "r"(a[2]), "r"(a[3]), "r"(b0), "r"(b1));
}

// -------------------------- fp32 -> bf16 hi/lo split ------------------------
__global__ __launch_bounds__(256) void split_kernel(
    const float4* __restrict__ src, __nv_bfloat162* __restrict__ hi,
    __nv_bfloat162* __restrict__ lo, int n4)
{
    int i = blockIdx.x * 256 + threadIdx.x;
    if (i >= n4) return;
    float4 v = src[i];
    bf16 h0 = __float2bfloat16(v.x), h1 = __float2bfloat16(v.y);
    bf16 h2 = __float2bfloat16(v.z), h3 = __float2bfloat16(v.w);
    __nv_bfloat162 a, b, c, d;
    a.x = h0; a.y = h1; b.x = h2; b.y = h3;
    c.x = __float2bfloat16(v.x - __bfloat162float(h0));
    c.y = __float2bfloat16(v.y - __bfloat162float(h1));
    d.x = __float2bfloat16(v.z - __bfloat162float(h2));
    d.y = __float2bfloat16(v.w - __bfloat162float(h3));
    hi[2 * i] = a; hi[2 * i + 1] = b;
    lo[2 * i] = c; lo[2 * i + 1] = d;
}

// -------------------------- layernorm --------------------------------------
__device__ __forceinline__ float block_sum_256(float v, float* red) {
    #pragma unroll
    for (int o = 16; o; o >>= 1) v += __shfl_xor_sync(0xffffffffu, v, o);
    if ((threadIdx.x & 31) == 0) red[threadIdx.x >> 5] = v;
    __syncthreads();
    float t = (threadIdx.x < 8) ? red[threadIdx.x] : 0.0f;
    if (threadIdx.x < 32) {
        #pragma unroll
        for (int o = 4; o; o >>= 1) t += __shfl_xor_sync(0xffffffffu, t, o);
        if (threadIdx.x == 0) red[0] = t;
    }
    __syncthreads();
    float r = red[0];
    __syncthreads();
    return r;
}

__global__ __launch_bounds__(256) void ln_kernel(
    const float* __restrict__ x, const float* __restrict__ g,
    const float* __restrict__ b, bf16* __restrict__ hi, bf16* __restrict__ lo)
{
    __shared__ float red[8];
    int row = blockIdx.x;
    const float4* xr = reinterpret_cast<const float4*>(x + (size_t)row * DM);
    float4 v = xr[threadIdx.x];

    float s = v.x + v.y + v.z + v.w;
    s = block_sum_256(s, red);
    float mean = s * (1.0f / DM);

    float dx = v.x - mean, dy = v.y - mean, dz = v.z - mean, dw = v.w - mean;
    float q = dx * dx + dy * dy + dz * dz + dw * dw;
    q = block_sum_256(q, red);
    float rstd = rsqrtf(q * (1.0f / DM) + 1e-5f);

    const float4* gr = reinterpret_cast<const float4*>(g);
    const float4* br = reinterpret_cast<const float4*>(b);
    float4 gv = gr[threadIdx.x], bv = br[threadIdx.x];
    float o0 = dx * rstd * gv.x + bv.x;
    float o1 = dy * rstd * gv.y + bv.y;
    float o2 = dz * rstd * gv.z + bv.z;
    float o3 = dw * rstd * gv.w + bv.w;

    bf16 h0 = __float2bfloat16(o0), h1 = __float2bfloat16(o1);
    bf16 h2 = __float2bfloat16(o2), h3 = __float2bfloat16(o3);
    __nv_bfloat162 a, b2, c, d;
    a.x = h0; a.y = h1; b2.x = h2; b2.y = h3;
    c.x = __float2bfloat16(o0 - __bfloat162float(h0));
    c.y = __float2bfloat16(o1 - __bfloat162float(h1));
    d.x = __float2bfloat16(o2 - __bfloat162float(h2));
    d.y = __float2bfloat16(o3 - __bfloat162float(h3));
    __nv_bfloat162* hp = reinterpret_cast<__nv_bfloat162*>(hi + (size_t)row * DM);
    __nv_bfloat162* lp = reinterpret_cast<__nv_bfloat162*>(lo + (size_t)row * DM);
    hp[2 * threadIdx.x] = a; hp[2 * threadIdx.x + 1] = b2;
    lp[2 * threadIdx.x] = c; lp[2 * threadIdx.x + 1] = d;
}

// -------------------------- mma.sync GEMM ----------------------------------
// C(M x N) = A(M x K) @ W(N x K)^T, bf16 hi/lo 3-product, fp32 accum.
// Tile 128x128, K-chunk 32, 8 warps (4m x 2n), warp tile 32x64.
// smem per stage: Ah|Al|Wh|Wl, each 128 rows x 32 bf16, row stride 40 elems.
// EPI: 0 fp32; 1 bias+softplus; 2 +res; 3 bias+gelu->hi/lo; 4 bias+res;
//      5 x_dbl (fp32 stride XC + dt hi/lo planes)

#define ROWB   80        // row stride bytes (40 bf16)
#define OFF_AH 0
#define OFF_AL 10240
#define OFF_WH 20480
#define OFF_WL 30720
#define STG    40960
#define GEMM_SMEM (2 * STG)

__device__ __forceinline__ void load_chunk(
    uint32_t sb, const bf16* __restrict__ Ah, const bf16* __restrict__ Al,
    const bf16* __restrict__ Wh, const bf16* __restrict__ Wl,
    int m0, int n0, int N, int K, int k0, int tid)
{
    #pragma unroll
    for (int r = 0; r < 2; r++) {
        int i = tid * 2 + r;                 // 0..511
        int row = i >> 2;
        int c = i & 3;
        uint32_t so = (uint32_t)(row * ROWB + c * 16);
        size_t ga = (size_t)(m0 + row) * K + k0 + c * 8;
        cp16(sb + OFF_AH + so, Ah + ga);
        cp16(sb + OFF_AL + so, Al + ga);
        bool ok = (n0 + row) < N;
        size_t gw = ok ? ((size_t)(n0 + row) * K + k0 + c * 8) : 0;
        cp16p(sb + OFF_WH + so, Wh + gw, ok);
        cp16p(sb + OFF_WL + so, Wl + gw, ok);
    }
}

template <int EPI>
__device__ __forceinline__ void epi2(
    int row, int c0, float v0, float v1, int N,
    const float* __restrict__ bias, const float* __restrict__ res,
    float* __restrict__ outf, bf16* __restrict__ oh, bf16* __restrict__ ol)
{
    if (EPI == 0) {
        *reinterpret_cast<float2*>(outf + (size_t)row * N + c0) = make_float2(v0, v1);
    } else if (EPI == 1) {
        v0 += bias[c0];     v0 = (v0 > 20.0f) ? v0 : log1pf(expf(v0));
        v1 += bias[c0 + 1]; v1 = (v1 > 20.0f) ? v1 : log1pf(expf(v1));
        *reinterpret_cast<float2*>(outf + (size_t)row * N + c0) = make_float2(v0, v1);
    } else if (EPI == 2) {
        float2 r = *reinterpret_cast<const float2*>(res + (size_t)row * N + c0);
        *reinterpret_cast<float2*>(outf + (size_t)row * N + c0) =
            make_float2(v0 + r.x, v1 + r.y);
    } else if (EPI == 3) {
        v0 += bias[c0];
        v1 += bias[c0 + 1];
        v0 = 0.5f * v0 * (1.0f + erff(v0 * 0.70710678118654752f));
        v1 = 0.5f * v1 * (1.0f + erff(v1 * 0.70710678118654752f));
        bf16 h0 = __float2bfloat16(v0), h1 = __float2bfloat16(v1);
        __nv_bfloat162 hh, ll;
        hh.x = h0; hh.y = h1;
        ll.x = __float2bfloat16(v0 - __bfloat162float(h0));
        ll.y = __float2bfloat16(v1 - __bfloat162float(h1));
        *reinterpret_cast<__nv_bfloat162*>(oh + (size_t)row * N + c0) = hh;
        *reinterpret_cast<__nv_bfloat162*>(ol + (size_t)row * N + c0) = ll;
    } else if (EPI == 4) {
        float2 r = *reinterpret_cast<const float2*>(res + (size_t)row * N + c0);
        *reinterpret_cast<float2*>(outf + (size_t)row * N + c0) =
            make_float2(v0 + bias[c0] + r.x, v1 + bias[c0 + 1] + r.y);
    } else {  // 5: x_dbl
        if (c0 < N) {
            *reinterpret_cast<float2*>(outf + (size_t)row * XC + c0) = make_float2(v0, v1);
            if (c0 < DTR) {
                bf16 h0 = __float2bfloat16(v0), h1 = __float2bfloat16(v1);
                __nv_bfloat162 hh, ll;
                hh.x = h0; hh.y = h1;
                ll.x = __float2bfloat16(v0 - __bfloat162float(h0));
                ll.y = __float2bfloat16(v1 - __bfloat162float(h1));
                *reinterpret_cast<__nv_bfloat162*>(oh + (size_t)row * DTR + c0) = hh;
                *reinterpret_cast<__nv_bfloat162*>(ol + (size_t)row * DTR + c0) = ll;
            }
        }
    }
}

template <int EPI>
__global__ __launch_bounds__(256) void gemm_mma(
    int N, int K,
    const bf16* __restrict__ Ah, const bf16* __restrict__ Al,
    const bf16* __restrict__ Wh, const bf16* __restrict__ Wl,
    const float* __restrict__ bias, const float* __restrict__ res,
    float* __restrict__ outf, bf16* __restrict__ oh, bf16* __restrict__ ol)
{
    extern __shared__ char smem[];
    uint32_t sb = smem_u32(smem);
    int tid = threadIdx.x;
    int lane = tid & 31, warp = tid >> 5;
    int warp_m = warp >> 1, warp_n = warp & 1;
    int m0 = blockIdx.y * 128, n0 = blockIdx.x * 128;

    float acc[2][8][4];
    #pragma unroll
    for (int i = 0; i < 2; i++)
        #pragma unroll
        for (int j = 0; j < 8; j++)
            #pragma unroll
            for (int q = 0; q < 4; q++) acc[i][j][q] = 0.0f;

    const int nc = K >> 5;
    load_chunk(sb, Ah, Al, Wh, Wl, m0, n0, N, K, 0, tid);
    CP_COMMIT();

    // per-warp ldmatrix base offsets (within a stage)
    uint32_t aoff = (uint32_t)((warp_m * 32 + (lane & 15)) * ROWB + (lane >> 4) * 16);
    int bn = warp_n * 64 + (lane & 7) + ((lane >> 4) & 1) * 8;
    uint32_t boff = (uint32_t)(bn * ROWB + ((lane >> 3) & 1) * 16);

    for (int c = 0; c < nc; c++) {
        if (c + 1 < nc) {
            load_chunk(sb + ((c + 1) & 1) * STG, Ah, Al, Wh, Wl,
                       m0, n0, N, K, (c + 1) << 5, tid);
            CP_COMMIT();
            CP_WAIT(1);
        } else {
            CP_WAIT(0);
        }
        __syncthreads();

        uint32_t st = sb + (c & 1) * STG;
        uint32_t aH = st + OFF_AH + aoff;
        uint32_t aL = st + OFF_AL + aoff;
        uint32_t bH = st + OFF_WH + boff;
        uint32_t bL = st + OFF_WL + boff;

        #pragma unroll
        for (int ks = 0; ks < 2; ks++) {
            uint32_t ah[2][4], al[2][4], bh[4][4], bl[4][4];
            LDSM4(ah[0], aH + ks * 32);
            LDSM4(ah[1], aH + 1280 + ks * 32);
            LDSM4(al[0], aL + ks * 32);
            LDSM4(al[1], aL + 1280 + ks * 32);
            #pragma unroll
            for (int np = 0; np < 4; np++) {
                LDSM4(bh[np], bH + np * 1280 + ks * 32);
                LDSM4(bl[np], bL + np * 1280 + ks * 32);
            }
            #pragma unroll
            for (int mt = 0; mt < 2; mt++) {
                #pragma unroll
                for (int np = 0; np < 4; np++) {
                    mma16816(acc[mt][2 * np],     ah[mt], bh[np][0], bh[np][1]);
                    mma16816(acc[mt][2 * np + 1], ah[mt], bh[np][2], bh[np][3]);
                    mma16816(acc[mt][2 * np],     al[mt], bh[np][0], bh[np][1]);
                    mma16816(acc[mt][2 * np + 1], al[mt], bh[np][2], bh[np][3]);
                    mma16816(acc[mt][2 * np],     ah[mt], bl[np][0], bl[np][1]);
                    mma16816(acc[mt][2 * np + 1], ah[mt], bl[np][2], bl[np][3]);
                }
            }
        }
        __syncthreads();
    }

    // epilogue
    int gid = lane >> 2, tig = lane & 3;
    #pragma unroll
    for (int mt = 0; mt < 2; mt++) {
        #pragma unroll
        for (int nt = 0; nt < 8; nt++) {
            int r0 = m0 + warp_m * 32 + mt * 16 + gid;
            int c0 = n0 + warp_n * 64 + nt * 8 + tig * 2;
            float* a4 = acc[mt][nt];
            epi2<EPI>(r0,     c0, a4[0], a4[1], N, bias, res, outf, oh, ol);
            epi2<EPI>(r0 + 8, c0, a4[2], a4[3], N, bias, res, outf, oh, ol);
        }
    }
}

// -------------------------- causal depthwise conv + SiLU -------------------
__global__ __launch_bounds__(256) void conv_silu_kernel(
    const float* __restrict__ conv_w, const float* __restrict__ conv_b)
{
    int idx = blockIdx.x * 256 + threadIdx.x;    // over NROWS*DI
    int d = idx & (DI - 1);
    int row = idx >> 11;
    int l = row & (SEQ - 1);
    float acc = conv_b[d];
    #pragma unroll
    for (int k = 0; k < 4; k++) {
        int ls = l - 3 + k;
        if (ls >= 0)
            acc += g_xz[(size_t)(row - 3 + k) * (2 * DI) + d] * conv_w[d * 4 + k];
    }
    float sg = 1.0f / (1.0f + expf(-acc));
    float v = acc * sg;
    bf16 h = __float2bfloat16(v);
    g_xa_hi[idx] = h;
    g_xa_lo[idx] = __float2bfloat16(v - __bfloat162float(h));
}

// -------------------------- selective scan ---------------------------------
__global__ __launch_bounds__(64) void scan_kernel(
    const float* __restrict__ A_log, const float* __restrict__ Dp)
{
    int d = blockIdx.x * 64 + threadIdx.x;
    int batch = blockIdx.y;

    float Aa[DSTATE];
    #pragma unroll
    for (int n = 0; n < DSTATE; n++) Aa[n] = -expf(A_log[d * DSTATE + n]);
    float Dd = Dp[d];

    float h[DSTATE];
    #pragma unroll
    for (int n = 0; n < DSTATE; n++) h[n] = 0.0f;

    __shared__ float bc[64][32];

    for (int l0 = 0; l0 < SEQ; l0 += 64) {
        int rowbase = batch * SEQ + l0;
        __syncthreads();
        for (int i = threadIdx.x; i < 64 * 32; i += 64) {
            int r = i >> 5, c = i & 31;
            bc[r][c] = g_xdbl[(size_t)(rowbase + r) * XC + DTR + c];
        }
        __syncthreads();

        for (int s = 0; s < 64; s++) {
            size_t idx = (size_t)(rowbase + s) * DI + d;
            float dlt = g_delta[idx];
            float u = __bfloat162float(g_xa_hi[idx]) + __bfloat162float(g_xa_lo[idx]);
            float du = dlt * u;
            float yt = 0.0f;
            #pragma unroll
            for (int n = 0; n < DSTATE; n++) {
                float dA = __expf(dlt * Aa[n]);
                h[n] = h[n] * dA + du * bc[s][n];
                yt += h[n] * bc[s][DSTATE + n];
            }
            float zv = g_xz[(size_t)(rowbase + s) * (2 * DI) + DI + d];
            float sg = 1.0f / (1.0f + __expf(-zv));
            float yv = (yt + u * Dd) * (zv * sg);
            bf16 yh = __float2bfloat16(yv);
            g_y_hi[idx] = yh;
            g_y_lo[idx] = __float2bfloat16(yv - __bfloat162float(yh));
        }
    }
}

// -------------------------- launch -----------------------------------------
extern "C" void kernel_launch(void* const* d_in, const int* in_sizes, int n_in,
                              void* d_out, int out_size)
{
    const float* x         = (const float*)d_in[0];
    const float* ln1_g     = (const float*)d_in[1];
    const float* ln1_b     = (const float*)d_in[2];
    const float* in_proj_w = (const float*)d_in[3];
    const float* conv_w    = (const float*)d_in[4];
    const float* conv_b    = (const float*)d_in[5];
    const float* x_proj_w  = (const float*)d_in[6];
    const float* dt_proj_w = (const float*)d_in[7];
    const float* dt_proj_b = (const float*)d_in[8];
    const float* A_log     = (const float*)d_in[9];
    const float* Dp        = (const float*)d_in[10];
    const float* out_proj_w= (const float*)d_in[11];
    const float* ln2_g     = (const float*)d_in[12];
    const float* ln2_b     = (const float*)d_in[13];
    const float* mlp_w1    = (const float*)d_in[14];
    const float* mlp_b1    = (const float*)d_in[15];
    const float* mlp_w2    = (const float*)d_in[16];
    const float* mlp_b2    = (const float*)d_in[17];
    float* out = (float*)d_out;

    cudaFuncSetAttribute(gemm_mma<0>, cudaFuncAttributeMaxDynamicSharedMemorySize, GEMM_SMEM);
    cudaFuncSetAttribute(gemm_mma<1>, cudaFuncAttributeMaxDynamicSharedMemorySize, GEMM_SMEM);
    cudaFuncSetAttribute(gemm_mma<2>, cudaFuncAttributeMaxDynamicSharedMemorySize, GEMM_SMEM);
    cudaFuncSetAttribute(gemm_mma<3>, cudaFuncAttributeMaxDynamicSharedMemorySize, GEMM_SMEM);
    cudaFuncSetAttribute(gemm_mma<4>, cudaFuncAttributeMaxDynamicSharedMemorySize, GEMM_SMEM);
    cudaFuncSetAttribute(gemm_mma<5>, cudaFuncAttributeMaxDynamicSharedMemorySize, GEMM_SMEM);

    float *pxz, *pxdbl, *pdelta, *px2;
    bf16 *phh, *phl, *pxah, *pxal, *pdth, *pdtl, *pyh, *pyl, *ph2h, *ph2l, *pm1h, *pm1l;
    bf16 *wiph, *wipl, *wxph, *wxpl, *wdth, *wdtl, *woph, *wopl, *wm1h, *wm1l, *wm2h, *wm2l;
    cudaGetSymbolAddress((void**)&pxz,    g_xz);
    cudaGetSymbolAddress((void**)&phh,    g_h_hi);   cudaGetSymbolAddress((void**)&phl,  g_h_lo);
    cudaGetSymbolAddress((void**)&pxah,   g_xa_hi);  cudaGetSymbolAddress((void**)&pxal, g_xa_lo);
    cudaGetSymbolAddress((void**)&pxdbl,  g_xdbl);
    cudaGetSymbolAddress((void**)&pdth,   g_dt_hi);  cudaGetSymbolAddress((void**)&pdtl, g_dt_lo);
    cudaGetSymbolAddress((void**)&pdelta, g_delta);
    cudaGetSymbolAddress((void**)&pyh,    g_y_hi);   cudaGetSymbolAddress((void**)&pyl,  g_y_lo);
    cudaGetSymbolAddress((void**)&px2,    g_x2);
    cudaGetSymbolAddress((void**)&ph2h,   g_h2_hi);  cudaGetSymbolAddress((void**)&ph2l, g_h2_lo);
    cudaGetSymbolAddress((void**)&pm1h,   g_m1_hi);  cudaGetSymbolAddress((void**)&pm1l, g_m1_lo);
    cudaGetSymbolAddress((void**)&wiph,   g_wip_h);  cudaGetSymbolAddress((void**)&wipl, g_wip_l);
    cudaGetSymbolAddress((void**)&wxph,   g_wxp_h);  cudaGetSymbolAddress((void**)&wxpl, g_wxp_l);
    cudaGetSymbolAddress((void**)&wdth,   g_wdt_h);  cudaGetSymbolAddress((void**)&wdtl, g_wdt_l);
    cudaGetSymbolAddress((void**)&woph,   g_wop_h);  cudaGetSymbolAddress((void**)&wopl, g_wop_l);
    cudaGetSymbolAddress((void**)&wm1h,   g_wm1_h);  cudaGetSymbolAddress((void**)&wm1l, g_wm1_l);
    cudaGetSymbolAddress((void**)&wm2h,   g_wm2_h);  cudaGetSymbolAddress((void**)&wm2l, g_wm2_l);

    // split weights into bf16 hi/lo planes
    auto split = [&](const float* src, bf16* hi, bf16* lo, int n) {
        split_kernel<<<(n / 4 + 255) / 256, 256>>>(
            (const float4*)src, (__nv_bfloat162*)hi, (__nv_bfloat162*)lo, n / 4);
    };
    split(in_proj_w,  wiph, wipl, 2 * DI * DM);
    split(x_proj_w,   wxph, wxpl, XC * DI);
    split(dt_proj_w,  wdth, wdtl, DI * DTR);
    split(out_proj_w, woph, wopl, DM * DI);
    split(mlp_w1,     wm1h, wm1l, HID * DM);
    split(mlp_w2,     wm2h, wm2l, DM * HID);

    // 1. LN1 -> h (hi/lo)
    ln_kernel<<<NROWS, 256>>>(x, ln1_g, ln1_b, phh, phl);

    // 2. in_proj -> xz fp32
    gemm_mma<0><<<dim3(2 * DI / 128, NROWS / 128), 256, GEMM_SMEM>>>(
        2 * DI, DM, phh, phl, wiph, wipl, nullptr, nullptr, pxz, nullptr, nullptr);

    // 3. conv1d + SiLU -> xa (hi/lo)
    conv_silu_kernel<<<(NROWS * DI) / 256, 256>>>(conv_w, conv_b);

    // 4. x_proj -> x_dbl fp32 + dt planes
    gemm_mma<5><<<dim3(1, NROWS / 128), 256, GEMM_SMEM>>>(
        XC, DI, pxah, pxal, wxph, wxpl, nullptr, nullptr, pxdbl, pdth, pdtl);

    // 5. dt_proj + softplus -> delta fp32
    gemm_mma<1><<<dim3(DI / 128, NROWS / 128), 256, GEMM_SMEM>>>(
        DI, DTR, pdth, pdtl, wdth, wdtl, dt_proj_b, nullptr, pdelta, nullptr, nullptr);

    // 6. selective scan -> y (hi/lo)
    scan_kernel<<<dim3(DI / 64, BATCH), 64>>>(A_log, Dp);

    // 7. out_proj + residual(x) -> x2 fp32
    gemm_mma<2><<<dim3(DM / 128, NROWS / 128), 256, GEMM_SMEM>>>(
        DM, DI, pyh, pyl, woph, wopl, nullptr, x, px2, nullptr, nullptr);

    // 8. LN2 -> h2 (hi/lo)
    ln_kernel<<<NROWS, 256>>>(px2, ln2_g, ln2_b, ph2h, ph2l);

    // 9. MLP up + GELU -> m1 (hi/lo)
    gemm_mma<3><<<dim3(HID / 128, NROWS / 128), 256, GEMM_SMEM>>>(
        HID, DM, ph2h, ph2l, wm1h, wm1l, mlp_b1, nullptr, nullptr, pm1h, pm1l);

    // 10. MLP down + bias + residual(x2) -> out
    gemm_mma<4><<<dim3(DM / 128, NROWS / 128), 256, GEMM_SMEM>>>(
        DM, HID, pm1h, pm1l, wm2h, wm2l, mlp_b2, px2, out, nullptr, nullptr);
}